// round 15
// baseline (speedup 1.0000x reference)
#include <cuda_runtime.h>
#include <cuda_bf16.h>
#include <cuda_fp16.h>
#include <cstdint>

#define D_IN  256
#define D_OUT 64
#define ROWS_TOTAL 200000   // N*K = 50000*4
#define NMAX  50048
#define EMAX  800000

// ---------------------------------------------------------------------------
// Static device scratch
// ---------------------------------------------------------------------------
__device__ __half g_support[(size_t)ROWS_TOTAL * D_OUT];  // fp16: 25.6 MB
__device__ int   g_deg[NMAX];
__device__ int   g_start[NMAX + 1];
__device__ int   g_cursor[NMAX];
__device__ int2  g_edges[EMAX];
// B fragments of W^T in mma.sync register layout:
// [kstep(16)][ntile(8)][lane(32)] -> uint4 {b0_hi, b1_hi, b0_lo, b1_lo}
__device__ __align__(16) uint4 g_bfrag[16 * 8 * 32];     // 64 KB

// ---------------------------------------------------------------------------
// MMA helpers (plain sm_80-level PTX: valid for compute_103 target)
// ---------------------------------------------------------------------------
__device__ __forceinline__ uint32_t smem_u32(const void* p) {
    uint32_t a;
    asm("{ .reg .u64 t; cvta.to.shared.u64 t, %1; cvt.u32.u64 %0, t; }" : "=r"(a) : "l"(p));
    return a;
}
__device__ __forceinline__ void ldsm_x4(uint32_t* r, uint32_t addr) {
    asm volatile("ldmatrix.sync.aligned.m8n8.x4.shared.b16 {%0,%1,%2,%3}, [%4];"
                 : "=r"(r[0]), "=r"(r[1]), "=r"(r[2]), "=r"(r[3]) : "r"(addr));
}
__device__ __forceinline__ void mma16816(float* c, const uint32_t* a,
                                         uint32_t b0, uint32_t b1) {
    asm volatile(
        "mma.sync.aligned.m16n8k16.row.col.f32.bf16.bf16.f32 "
        "{%0,%1,%2,%3}, {%4,%5,%6,%7}, {%8,%9}, {%0,%1,%2,%3};"
        : "+f"(c[0]), "+f"(c[1]), "+f"(c[2]), "+f"(c[3])
        : "r"(a[0]), "r"(a[1]), "r"(a[2]), "r"(a[3]), "r"(b0), "r"(b1));
}

// ---------------------------------------------------------------------------
// B prep: W[256,64] -> hi/lo bf16 fragments in mma register layout
// ---------------------------------------------------------------------------
__global__ void bprep_kernel(const float* __restrict__ w)
{
    int i = blockIdx.x * 256 + threadIdx.x;
    if (i >= 16 * 8 * 32) return;
    int lane = i & 31;
    int n  = ((i >> 5) & 7) * 8 + (lane >> 2);
    int k0 = (i >> 8) * 16 + (lane & 3) * 2;

    float v00 = w[(k0    ) * 64 + n];
    float v01 = w[(k0 + 1) * 64 + n];
    float v10 = w[(k0 + 8) * 64 + n];
    float v11 = w[(k0 + 9) * 64 + n];

    __nv_bfloat162 h0 = __floats2bfloat162_rn(v00, v01);
    __nv_bfloat162 h1 = __floats2bfloat162_rn(v10, v11);
    float2 f0 = __bfloat1622float2(h0);
    float2 f1 = __bfloat1622float2(h1);
    __nv_bfloat162 l0 = __floats2bfloat162_rn(v00 - f0.x, v01 - f0.y);
    __nv_bfloat162 l1 = __floats2bfloat162_rn(v10 - f1.x, v11 - f1.y);

    uint4 r;
    r.x = *(uint32_t*)&h0;  r.y = *(uint32_t*)&h1;
    r.z = *(uint32_t*)&l0;  r.w = *(uint32_t*)&l1;
    g_bfrag[i] = r;
}

// ---------------------------------------------------------------------------
// GEMM via mma.sync bf16 hi/lo split; epilogue converts to fp16 support.
// Block: 64 rows, 128 threads (4 warps x 16 rows).
// ---------------------------------------------------------------------------
#define AROW 264                       // elements; 528-byte stride
#define A_IMG (64 * AROW * 2)          // 33792 bytes per image
#define GEMM_SMEM (2 * A_IMG)          // 67584 bytes

__global__ void __launch_bounds__(128, 3)
gemm_mma_kernel(const float* __restrict__ x)
{
    extern __shared__ __align__(16) unsigned char smem[];
    __nv_bfloat16* a_hi = (__nv_bfloat16*)smem;
    __nv_bfloat16* a_lo = (__nv_bfloat16*)(smem + A_IMG);

    const int tid  = threadIdx.x;
    const int wid  = tid >> 5;
    const int lane = tid & 31;
    const int m0   = blockIdx.x * 64;

    // --- load x tile [64][256] f32 -> hi/lo bf16 smem ---
    const float4* xs = (const float4*)x + (size_t)m0 * 64;
    #pragma unroll 4
    for (int i = tid; i < 4096; i += 128) {
        const int r  = i >> 6;
        const int c4 = i & 63;
        float4 v = xs[(size_t)r * 64 + c4];

        __nv_bfloat162 h01 = __floats2bfloat162_rn(v.x, v.y);
        __nv_bfloat162 h23 = __floats2bfloat162_rn(v.z, v.w);
        float2 f01 = __bfloat1622float2(h01);
        float2 f23 = __bfloat1622float2(h23);
        __nv_bfloat162 l01 = __floats2bfloat162_rn(v.x - f01.x, v.y - f01.y);
        __nv_bfloat162 l23 = __floats2bfloat162_rn(v.z - f23.x, v.w - f23.y);

        uint32_t* dh = (uint32_t*)(a_hi + r * AROW + c4 * 4);
        uint32_t* dl = (uint32_t*)(a_lo + r * AROW + c4 * 4);
        dh[0] = *(uint32_t*)&h01;  dh[1] = *(uint32_t*)&h23;
        dl[0] = *(uint32_t*)&l01;  dl[1] = *(uint32_t*)&l23;
    }
    __syncthreads();

    // --- per-warp m16n64 tile, K=256 in 16 k-steps ---
    const int mat = lane >> 3;
    const int ar  = (wid << 4) + (lane & 7) + ((mat & 1) << 3);
    const uint32_t aoff = (uint32_t)(ar * AROW + (mat >> 1) * 8) * 2u;
    uint32_t addr_hi = smem_u32(a_hi) + aoff;
    uint32_t addr_lo = smem_u32(a_lo) + aoff;

    float c[8][4];
    #pragma unroll
    for (int nt = 0; nt < 8; ++nt)
        c[nt][0] = c[nt][1] = c[nt][2] = c[nt][3] = 0.f;

    #pragma unroll 1
    for (int ks = 0; ks < 16; ++ks) {
        uint32_t ah[4], al[4];
        ldsm_x4(ah, addr_hi + ks * 32);
        ldsm_x4(al, addr_lo + ks * 32);
        const uint4* bf = g_bfrag + ks * 256 + lane;
        #pragma unroll
        for (int nt = 0; nt < 8; ++nt) {
            const uint4 b = __ldg(bf + nt * 32);
            mma16816(c[nt], ah, b.x, b.y);   // Ahi * Bhi
            mma16816(c[nt], ah, b.z, b.w);   // Ahi * Blo
            mma16816(c[nt], al, b.x, b.y);   // Alo * Bhi
        }
    }

    // --- epilogue: fragment -> fp16 g_support (half2 stores) ---
    const int r0 = m0 + (wid << 4) + (lane >> 2);
    const int cb = (lane & 3) * 2;
    #pragma unroll
    for (int nt = 0; nt < 8; ++nt) {
        const int col = nt * 8 + cb;
        *(__half2*)(g_support + (size_t)r0 * 64 + col) =
            __floats2half2_rn(c[nt][0], c[nt][1]);
        *(__half2*)(g_support + (size_t)(r0 + 8) * 64 + col) =
            __floats2half2_rn(c[nt][2], c[nt][3]);
    }
}

// ---------------------------------------------------------------------------
// CSR build
// ---------------------------------------------------------------------------
__global__ void zero_deg_kernel(int n)
{
    int i = blockIdx.x * blockDim.x + threadIdx.x;
    if (i < n) g_deg[i] = 0;
}

__global__ void count_kernel(const int* __restrict__ adj_rows, int E)
{
    int e = blockIdx.x * blockDim.x + threadIdx.x;
    if (e < E) atomicAdd(&g_deg[adj_rows[e]], 1);
}

// Fused exclusive scan over g_deg: single block, 1024 threads, sequential
// chunks + block scan. Writes g_start[0..n] and g_cursor[0..n-1].
__global__ void __launch_bounds__(1024)
scan_all_kernel(int n, int E)
{
    __shared__ int s[1024];
    const int t = threadIdx.x;
    const int chunk = (n + 1023) / 1024;
    const int i0 = t * chunk;

    int sum = 0;
    for (int j = 0; j < chunk; ++j) {
        int i = i0 + j;
        if (i < n) sum += g_deg[i];
    }
    s[t] = sum;
    __syncthreads();
#pragma unroll
    for (int off = 1; off < 1024; off <<= 1) {
        int add = (t >= off) ? s[t - off] : 0;
        __syncthreads();
        s[t] += add;
        __syncthreads();
    }
    int run = s[t] - sum;   // exclusive prefix of this chunk
    for (int j = 0; j < chunk; ++j) {
        int i = i0 + j;
        if (i < n) {
            g_start[i]  = run;
            g_cursor[i] = run;
            run += g_deg[i];
        }
    }
    if (t == 0) g_start[n] = E;
}

__global__ void fill_kernel(const int* __restrict__ adj_rows,
                            const int* __restrict__ adj_cols,
                            const float* __restrict__ adj_vals, int E)
{
    int e = blockIdx.x * blockDim.x + threadIdx.x;
    if (e < E) {
        int r   = adj_rows[e];
        int pos = atomicAdd(&g_cursor[r], 1);
        g_edges[pos] = make_int2(adj_cols[e], __float_as_int(adj_vals[e]));
    }
}

// ---------------------------------------------------------------------------
// Gather with fused ReLU. 64 threads per output row; each thread owns 4
// output floats (reads 4 fp16 = 8B per edge). 4-edge unroll for MLP.
// ---------------------------------------------------------------------------
__global__ void __launch_bounds__(256)
gather_kernel(float* __restrict__ out, int n)
{
    const int row = blockIdx.x * 4 + (threadIdx.x >> 6);
    const int j   = threadIdx.x & 63;
    if (row >= n) return;

    const int start = g_start[row];
    const int end   = g_start[row + 1];

    const uint2* sup = (const uint2*)g_support;   // 64 uint2 per 256-half row

    float4 acc = make_float4(0.f, 0.f, 0.f, 0.f);

    int p = start;
    for (; p + 3 < end; p += 4) {
        const int2 e0 = __ldg(&g_edges[p]);
        const int2 e1 = __ldg(&g_edges[p + 1]);
        const int2 e2 = __ldg(&g_edges[p + 2]);
        const int2 e3 = __ldg(&g_edges[p + 3]);
        const uint2 r0 = __ldg(sup + (size_t)e0.x * 64 + j);
        const uint2 r1 = __ldg(sup + (size_t)e1.x * 64 + j);
        const uint2 r2 = __ldg(sup + (size_t)e2.x * 64 + j);
        const uint2 r3 = __ldg(sup + (size_t)e3.x * 64 + j);
        const float v0 = __int_as_float(e0.y), v1 = __int_as_float(e1.y);
        const float v2 = __int_as_float(e2.y), v3 = __int_as_float(e3.y);

        float2 a0 = __half22float2(*(const __half2*)&r0.x);
        float2 b0 = __half22float2(*(const __half2*)&r0.y);
        acc.x = fmaf(v0, a0.x, acc.x); acc.y = fmaf(v0, a0.y, acc.y);
        acc.z = fmaf(v0, b0.x, acc.z); acc.w = fmaf(v0, b0.y, acc.w);

        float2 a1 = __half22float2(*(const __half2*)&r1.x);
        float2 b1 = __half22float2(*(const __half2*)&r1.y);
        acc.x = fmaf(v1, a1.x, acc.x); acc.y = fmaf(v1, a1.y, acc.y);
        acc.z = fmaf(v1, b1.x, acc.z); acc.w = fmaf(v1, b1.y, acc.w);

        float2 a2 = __half22float2(*(const __half2*)&r2.x);
        float2 b2 = __half22float2(*(const __half2*)&r2.y);
        acc.x = fmaf(v2, a2.x, acc.x); acc.y = fmaf(v2, a2.y, acc.y);
        acc.z = fmaf(v2, b2.x, acc.z); acc.w = fmaf(v2, b2.y, acc.w);

        float2 a3 = __half22float2(*(const __half2*)&r3.x);
        float2 b3 = __half22float2(*(const __half2*)&r3.y);
        acc.x = fmaf(v3, a3.x, acc.x); acc.y = fmaf(v3, a3.y, acc.y);
        acc.z = fmaf(v3, b3.x, acc.z); acc.w = fmaf(v3, b3.y, acc.w);
    }
    for (; p < end; ++p) {
        const int2 e0 = __ldg(&g_edges[p]);
        const float v0 = __int_as_float(e0.y);
        const uint2 r0 = __ldg(sup + (size_t)e0.x * 64 + j);
        float2 a0 = __half22float2(*(const __half2*)&r0.x);
        float2 b0 = __half22float2(*(const __half2*)&r0.y);
        acc.x = fmaf(v0, a0.x, acc.x); acc.y = fmaf(v0, a0.y, acc.y);
        acc.z = fmaf(v0, b0.x, acc.z); acc.w = fmaf(v0, b0.y, acc.w);
    }

    acc.x = fmaxf(acc.x, 0.f); acc.y = fmaxf(acc.y, 0.f);
    acc.z = fmaxf(acc.z, 0.f); acc.w = fmaxf(acc.w, 0.f);
    ((float4*)(out + (size_t)row * 256))[j] = acc;
}

// ---------------------------------------------------------------------------
// Launch: single stream, capture-safe.
// ---------------------------------------------------------------------------
extern "C" void kernel_launch(void* const* d_in, const int* in_sizes, int n_in,
                              void* d_out, int out_size)
{
    const float* x  = (const float*)d_in[0];
    const float* w  = (const float*)d_in[1];
    const int*   ar = (const int*)d_in[2];
    const int*   ac = (const int*)d_in[3];
    const float* av = (const float*)d_in[4];
    float*       out = (float*)d_out;

    const int rows = in_sizes[0] / D_IN;          // 200000
    const int E    = in_sizes[2];                 // 800000
    const int N    = out_size / 256;              // 50000

    cudaFuncSetAttribute(gemm_mma_kernel,
                         cudaFuncAttributeMaxDynamicSharedMemorySize, GEMM_SMEM);

    // GEMM (tensor cores via mma.sync, bf16 hi/lo split) -> fp16 support
    bprep_kernel<<<16, 256>>>(w);
    gemm_mma_kernel<<<rows / 64, 128, GEMM_SMEM>>>(x);

    // CSR build
    zero_deg_kernel<<<(N + 255) / 256, 256>>>(N);
    count_kernel<<<(E + 255) / 256, 256>>>(ar, E);
    scan_all_kernel<<<1, 1024>>>(N, E);
    fill_kernel<<<(E + 255) / 256, 256>>>(ar, ac, av, E);

    // register-accumulating gather with fused ReLU
    gather_kernel<<<(N + 3) / 4, 256>>>(out, N);
}